// round 13
// baseline (speedup 1.0000x reference)
#include <cuda_runtime.h>
#include <cstdint>

// MultiScaleDeformableAttention — smem-staged setup + depth-2 gather pipeline.
//
// value:              (8, 22223, 8, 32)  float32
// sampling_locations: (8, 900, 8, 4, 4, 2) float32
// attention_weights:  (8, 900, 8, 4, 4) float32
// out:                (8, 900, 256) float32
//
// Block = 32 tuples x 8 threads (c4 channel-groups).
// Phase A: 256 threads each compute bilinear setup for one (tuple, point-pair)
//          -> offsets + aw-folded weights into padded smem (no 8x redundancy).
// Phase B: per (tuple, c4) thread, 16 points through the proven 3-slot
//          rotating register pipeline (loads for p+2 issued while consuming p,
//          ~12 LDG.128 in flight/warp). Setup per point = 2 broadcast LDS.128.

#define NQ 900
#define NH 8
#define ND 32
#define BS 8
#define NKEYS 22223
#define NTUP (BS * NQ * NH)        // 57600 tuples
#define TUPB 32                    // tuples per block
#define TPAD 33                    // padded tuple stride (bank-conflict-free)
#define VSTRIDE (NH * ND)          // 256 floats per key

__device__ __forceinline__ void point_setup(
    float lx, float ly, float w,
    int H, int W, int S,
    int& o00, int& o10, int& o01, int& o11,
    float& w00, float& w10, float& w01, float& w11)
{
    const float x = lx * (float)W - 0.5f;
    const float y = ly * (float)H - 0.5f;
    const float x0f = floorf(x);
    const float y0f = floorf(y);
    const int x0 = (int)x0f;
    const int y0 = (int)y0f;
    const int x1 = x0 + 1;
    const int y1 = y0 + 1;
    const float fx1 = x - x0f;
    const float fy1 = y - y0f;
    const float fx0 = 1.0f - fx1;
    const float fy0 = 1.0f - fy1;

    // zero weight factor for OOB corners; fold aw into the y factors.
    const float mx0 = (x0 >= 0 && x0 < W) ? fx0 : 0.0f;
    const float mx1 = (x1 >= 0 && x1 < W) ? fx1 : 0.0f;
    const float my0 = (y0 >= 0 && y0 < H) ? fy0 * w : 0.0f;
    const float my1 = (y1 >= 0 && y1 < H) ? fy1 * w : 0.0f;

    const int cx0 = min(max(x0, 0), W - 1);
    const int cx1 = min(max(x1, 0), W - 1);
    const int cy0 = min(max(y0, 0), H - 1);
    const int cy1 = min(max(y1, 0), H - 1);

    const int r0 = S + cy0 * W;
    const int r1 = S + cy1 * W;

    o00 = (r0 + cx0) * VSTRIDE;
    o10 = (r0 + cx1) * VSTRIDE;
    o01 = (r1 + cx0) * VSTRIDE;
    o11 = (r1 + cx1) * VSTRIDE;

    w00 = mx0 * my0;
    w10 = mx1 * my0;
    w01 = mx0 * my1;
    w11 = mx1 * my1;
}

__global__ __launch_bounds__(256, 3)   // 85 regs/thread: keep pipeline in regs
void msda_kernel(const float* __restrict__ value,
                 const float* __restrict__ loc,
                 const float* __restrict__ aw,
                 float* __restrict__ out)
{
    __shared__ int4   s_off[16][TPAD];   // [point][tuple] corner offsets
    __shared__ float4 s_wt [16][TPAD];   // [point][tuple] folded weights

    const int tid = threadIdx.x;
    const int t0  = blockIdx.x * TUPB;   // first tuple of this block

    // ---------------- Phase A: per-tuple setup, computed once ----------------
    {
        const int tl   = tid >> 3;           // tuple_local 0..31
        const int pair = tid & 7;            // point-pair 0..7 -> points 2p,2p+1
        const int t    = t0 + tl;
        const int p0   = pair * 2;
        const int l    = p0 >> 2;            // both points of a pair share a level

        const int H = (l == 0) ? 100 : (l == 1) ? 50 : (l == 2) ? 25 : 13;
        const int W = (l == 0) ? 167 : (l == 1) ? 84 : (l == 2) ? 42 : 21;
        const int S = (l == 0) ? 0 : (l == 1) ? 16700 : (l == 2) ? 20900 : 21950;

        // loc: 2 points = one float4; aw: 2 points = one float2
        const float4 lp = __ldg((const float4*)(loc + (size_t)t * 32) + pair);
        const float2 wp = __ldg((const float2*)(aw  + (size_t)t * 16) + pair);

        int   o00, o10, o01, o11;
        float w00, w10, w01, w11;

        point_setup(lp.x, lp.y, wp.x, H, W, S,
                    o00, o10, o01, o11, w00, w10, w01, w11);
        s_off[p0][tl] = make_int4(o00, o10, o01, o11);
        s_wt [p0][tl] = make_float4(w00, w10, w01, w11);

        point_setup(lp.z, lp.w, wp.y, H, W, S,
                    o00, o10, o01, o11, w00, w10, w01, w11);
        s_off[p0 + 1][tl] = make_int4(o00, o10, o01, o11);
        s_wt [p0 + 1][tl] = make_float4(w00, w10, w01, w11);
    }
    __syncthreads();

    // ---------------- Phase B: pipelined gather + FMA ----------------
    const int tl = tid >> 3;             // tuple_local
    const int c4 = tid & 7;              // channel group (4 floats)
    const int t  = t0 + tl;

    const int h = t & 7;
    const int b = (t >> 3) / NQ;

    const float* __restrict__ vbase =
        value + (size_t)b * (NKEYS * NH * ND) + h * ND + c4 * 4;

    // 3-slot rotating pipeline (fully unrolled -> registers)
    float4 v00[3], v10[3], v01[3], v11[3];
    float4 wt[3];

    auto issue = [&](int pi, int s) {
        const int4   o = s_off[pi][tl];     // broadcast LDS.128
        wt[s]          = s_wt [pi][tl];     // broadcast LDS.128
        v00[s] = __ldg((const float4*)(vbase + o.x));
        v10[s] = __ldg((const float4*)(vbase + o.y));
        v01[s] = __ldg((const float4*)(vbase + o.z));
        v11[s] = __ldg((const float4*)(vbase + o.w));
    };

    issue(0, 0);
    issue(1, 1);

    float4 acc0 = make_float4(0.f, 0.f, 0.f, 0.f);
    float4 acc1 = make_float4(0.f, 0.f, 0.f, 0.f);

    #pragma unroll
    for (int pi = 0; pi < 16; ++pi) {
        const int cur = pi % 3;
        if (pi < 14)
            issue(pi + 2, (pi + 2) % 3);

        const float a = wt[cur].x, bw = wt[cur].y, c = wt[cur].z, d = wt[cur].w;
        const float4 p00 = v00[cur], p10 = v10[cur], p01 = v01[cur], p11 = v11[cur];
        float4& acc = (pi & 1) ? acc1 : acc0;

        acc.x = fmaf(a, p00.x, acc.x);
        acc.y = fmaf(a, p00.y, acc.y);
        acc.z = fmaf(a, p00.z, acc.z);
        acc.w = fmaf(a, p00.w, acc.w);

        acc.x = fmaf(bw, p10.x, acc.x);
        acc.y = fmaf(bw, p10.y, acc.y);
        acc.z = fmaf(bw, p10.z, acc.z);
        acc.w = fmaf(bw, p10.w, acc.w);

        acc.x = fmaf(c, p01.x, acc.x);
        acc.y = fmaf(c, p01.y, acc.y);
        acc.z = fmaf(c, p01.z, acc.z);
        acc.w = fmaf(c, p01.w, acc.w);

        acc.x = fmaf(d, p11.x, acc.x);
        acc.y = fmaf(d, p11.y, acc.y);
        acc.z = fmaf(d, p11.z, acc.z);
        acc.w = fmaf(d, p11.w, acc.w);
    }

    float4 r;
    r.x = acc0.x + acc1.x;
    r.y = acc0.y + acc1.y;
    r.z = acc0.z + acc1.z;
    r.w = acc0.w + acc1.w;

    ((float4*)out)[(size_t)t * 8 + c4] = r;
}

extern "C" void kernel_launch(void* const* d_in, const int* in_sizes, int n_in,
                              void* d_out, int out_size)
{
    const float* value = (const float*)d_in[0];
    const float* loc   = (const float*)d_in[1];
    const float* aw    = (const float*)d_in[2];
    float* out = (float*)d_out;

    const int threads = 256;                 // 32 tuples per block
    const int blocks  = NTUP / TUPB;         // 1800 (exact)
    msda_kernel<<<blocks, threads>>>(value, loc, aw, out);
}